// round 16
// baseline (speedup 1.0000x reference)
#include <cuda_runtime.h>
#include <cuda_fp16.h>
#include <cstdint>

// ---------------- problem constants ----------------
#define BB 4
#define SS 2048
#define HH 8
#define DD 64
#define HID 512
#define MT (BB*SS)   // 8192

// scratch (all fp16 intermediates)
__device__ __half g_X[MT*HID];        // x fp16
__device__ __half g_Wh[4*HID*HID];    // Wq,Wk,Wv,Wo fp16
__device__ __half g_Q[MT*HID];        // [b,h,s,d] pre-scaled by 0.125*log2e
__device__ __half g_K[MT*HID];        // [b,h,s,d]
__device__ __half g_V[MT*HID];        // [b,h,s,d]
__device__ __half g_C[MT*HID];        // ctx [b,s,hid] fp16

#define QSCALE 0.18033688011112042f   // 0.125 * log2(e)

__device__ __forceinline__ float ex2(float x){
    float r; asm("ex2.approx.ftz.f32 %0, %1;" : "=f"(r) : "f"(x)); return r;
}
// packed fp16 ex2: two exponentials in ONE MUFU op
__device__ __forceinline__ uint32_t hex2(uint32_t x){
    uint32_t r; asm("ex2.approx.f16x2 %0, %1;" : "=r"(r) : "r"(x)); return r;
}
__device__ __forceinline__ uint32_t pkhf(float lo, float hi){
    uint32_t d; asm("cvt.rn.f16x2.f32 %0, %1, %2;" : "=r"(d) : "f"(hi), "f"(lo)); return d;
}
__device__ __forceinline__ uint32_t smem_u32(const void* p){
    uint32_t a;
    asm("{ .reg .u64 t; cvta.to.shared.u64 t, %1; cvt.u32.u64 %0, t; }" : "=r"(a) : "l"(p));
    return a;
}
__device__ __forceinline__ void cpasync16(uint32_t dst, const void* src){
    asm volatile("cp.async.cg.shared.global [%0], [%1], 16;" :: "r"(dst), "l"(src) : "memory");
}
#define CP_COMMIT() asm volatile("cp.async.commit_group;" ::: "memory")
#define CP_WAIT0()  asm volatile("cp.async.wait_group 0;" ::: "memory")

// mma.sync m16n8k16 f16 (fp32 accumulate)
__device__ __forceinline__ void mma16(float* c, const uint32_t* a, const uint32_t* b){
    asm volatile("mma.sync.aligned.m16n8k16.row.col.f32.f16.f16.f32 "
        "{%0,%1,%2,%3}, {%4,%5,%6,%7}, {%8,%9}, {%0,%1,%2,%3};"
        : "+f"(c[0]), "+f"(c[1]), "+f"(c[2]), "+f"(c[3])
        : "r"(a[0]), "r"(a[1]), "r"(a[2]), "r"(a[3]), "r"(b[0]), "r"(b[1]));
}
__device__ __forceinline__ void ldsm4(uint32_t* r, uint32_t addr){
    asm volatile("ldmatrix.sync.aligned.m8n8.x4.shared.b16 {%0,%1,%2,%3}, [%4];"
        : "=r"(r[0]), "=r"(r[1]), "=r"(r[2]), "=r"(r[3]) : "r"(addr));
}
__device__ __forceinline__ void ldsm4t(uint32_t* r, uint32_t addr){
    asm volatile("ldmatrix.sync.aligned.m8n8.x4.trans.shared.b16 {%0,%1,%2,%3}, [%4];"
        : "=r"(r[0]), "=r"(r[1]), "=r"(r[2]), "=r"(r[3]) : "r"(addr));
}

// ---------------------------------------------------------------------------
// fp32 -> fp16 pre-conversion (rounding points identical to in-GEMM cvt).
// ---------------------------------------------------------------------------
__global__ __launch_bounds__(256)
void cvt_inputs(const float* __restrict__ x,
                const float* __restrict__ Wq, const float* __restrict__ Wk,
                const float* __restrict__ Wv, const float* __restrict__ Wo,
                __half* __restrict__ Xh, __half* __restrict__ Wh)
{
    const int flat = blockIdx.x * 256 + threadIdx.x;   // float4 index
    const float* src; uint2* dst; int off;
    if (flat < 1048576) { src = x; dst = (uint2*)Xh; off = flat; }
    else {
        const int w = (flat - 1048576) >> 16;
        off = (flat - 1048576) & 65535;
        src = (w == 0) ? Wq : (w == 1) ? Wk : (w == 2) ? Wv : Wo;
        dst = (uint2*)(Wh + (size_t)w * HID * HID);
    }
    float4 v = ((const float4*)src)[off];
    dst[off] = make_uint2(pkhf(v.x, v.y), pkhf(v.z, v.w));
}

// ---------------------------------------------------------------------------
// GEMM core (fp16 in gmem): out = A[M,512] @ W[Nblk,512]^T + bias.
// CTA 128x128, BK=64, 8 warps = 4(M) x 2(N).  2-stage cp.async pipeline with
// ONE __syncthreads per chunk.
// Tile stride 72 halves = 144 B (LDSM conflict-free).
// MODE 0: fp32 [m][512]   MODE 1: K fp16 [b,h,s,d]   MODE 2: Q scaled fp16
// MODE 3: V fp16 [b,h,s,d]
// ---------------------------------------------------------------------------
#define BK 64
#define GSTR_B 144
#define GAB_B (128*GSTR_B)       // per-matrix stage bytes = 18432
#define GSTAGE_B (2*GAB_B)       // 36864
#define NCH (HID/BK)             // 8

template<int MODE>
__device__ __forceinline__ void gemm_core(
    const __half* __restrict__ A, const __half* __restrict__ W,
    const float* __restrict__ bias, void* __restrict__ outv,
    char* smraw, int m0, int n0)
{
    float* bs = (float*)(smraw + 2*GSTAGE_B);
    const uint32_t sb = smem_u32(smraw);

    const int tid = threadIdx.x;
    const int lane = tid & 31, warp = tid >> 5;
    const int g = lane >> 2, t4 = lane & 3;
    const int warpM = warp >> 1, warpN = warp & 1;
    const int lm = lane >> 3, lr8 = lane & 7;
    const uint32_t laneA = ((uint32_t)((lm & 1)*8 + lr8))*GSTR_B + (uint32_t)(lm >> 1)*16;
    const uint32_t laneB = ((uint32_t)((lm >> 1)*8 + lr8))*GSTR_B + (uint32_t)(lm & 1)*16;

    if (tid < 128) bs[tid] = bias[n0 + tid];

    float c[2][8][4];
    #pragma unroll
    for (int i = 0; i < 2; i++)
        #pragma unroll
        for (int j = 0; j < 8; j++)
            #pragma unroll
            for (int k = 0; k < 4; k++) c[i][j][k] = 0.0f;

    const __half* Abase = A + (size_t)m0 * HID;
    const __half* Wbase = W + (size_t)n0 * HID;

    // prologue: chunk 0 -> stage 0
    #pragma unroll
    for (int i = 0; i < 4; i++) {
        const int cc = tid + i*256;
        const int row = cc >> 3, col = cc & 7;
        cpasync16(sb + row*GSTR_B + col*16, Abase + (size_t)row*HID + col*8);
        cpasync16(sb + GAB_B + row*GSTR_B + col*16, Wbase + (size_t)row*HID + col*8);
    }
    CP_COMMIT();

    #pragma unroll 1
    for (int ch = 0; ch < NCH; ch++) {
        const int cur = ch & 1;
        CP_WAIT0();
        __syncthreads();

        if (ch < NCH-1) {
            const uint32_t st = sb + (cur^1)*GSTAGE_B;
            const int koff = (ch+1)*BK;
            #pragma unroll
            for (int i = 0; i < 4; i++) {
                const int cc = tid + i*256;
                const int row = cc >> 3, col = cc & 7;
                cpasync16(st + row*GSTR_B + col*16, Abase + (size_t)row*HID + koff + col*8);
                cpasync16(st + GAB_B + row*GSTR_B + col*16, Wbase + (size_t)row*HID + koff + col*8);
            }
            CP_COMMIT();
        }

        const uint32_t abase = sb + cur*GSTAGE_B + (uint32_t)(warpM*32)*GSTR_B + laneA;
        const uint32_t bbase = sb + cur*GSTAGE_B + GAB_B + (uint32_t)(warpN*64)*GSTR_B + laneB;
        #pragma unroll
        for (int ks = 0; ks < 4; ks++) {      // 4 k-steps of 16
            uint32_t af[2][4];
            ldsm4(af[0], abase + ks*32);
            ldsm4(af[1], abase + 16*GSTR_B + ks*32);
            #pragma unroll
            for (int p = 0; p < 4; p++) {     // 16-n blocks
                uint32_t bf[4];
                ldsm4(bf, bbase + (uint32_t)(p*16)*GSTR_B + ks*32);
                mma16(c[0][2*p],   af[0], bf);
                mma16(c[0][2*p+1], af[0], bf+2);
                mma16(c[1][2*p],   af[1], bf);
                mma16(c[1][2*p+1], af[1], bf+2);
            }
        }
    }

    // epilogue
    #pragma unroll
    for (int mt = 0; mt < 2; mt++) {
        const int row = m0 + warpM*32 + mt*16 + g;
        #pragma unroll
        for (int nt = 0; nt < 8; nt++) {
            const int lc2 = warpN*64 + nt*8 + 2*t4;
            const float b0 = bs[lc2], b1 = bs[lc2+1];
            float2 v0 = make_float2(c[mt][nt][0] + b0, c[mt][nt][1] + b1);
            float2 v1 = make_float2(c[mt][nt][2] + b0, c[mt][nt][3] + b1);
            if (MODE == 2) { v0.x *= QSCALE; v0.y *= QSCALE; v1.x *= QSCALE; v1.y *= QSCALE; }
            if (MODE == 0) {
                float* out = (float*)outv;
                *(float2*)&out[(size_t)row * HID + n0 + lc2] = v0;
                *(float2*)&out[(size_t)(row+8) * HID + n0 + lc2] = v1;
            } else {
                __half* out = (__half*)outv;
                const int bi = row >> 11, s = row & 2047;
                const int cg = n0 + lc2;
                const int h = cg >> 6, d = cg & 63;
                __half* p = out + (((size_t)(bi*HH + h) * SS) + s) * DD + d;
                *(uint32_t*)p = pkhf(v0.x, v0.y);
                *(uint32_t*)(p + 8*DD) = pkhf(v1.x, v1.y);
            }
        }
    }
}

// fused QKV projection
__global__ __launch_bounds__(256, 2)
void gemm_qkv(const __half* __restrict__ x, const __half* __restrict__ Wh,
              const float* __restrict__ bq, const float* __restrict__ bk,
              const float* __restrict__ bv,
              __half* __restrict__ Qp, __half* __restrict__ Kp, __half* __restrict__ Vp)
{
    extern __shared__ char smraw[];
    const int m0 = blockIdx.x << 7, n0 = blockIdx.y << 7;
    if (blockIdx.z == 0)      gemm_core<2>(x, Wh,             bq, Qp, smraw, m0, n0);
    else if (blockIdx.z == 1) gemm_core<1>(x, Wh +   HID*HID, bk, Kp, smraw, m0, n0);
    else                      gemm_core<3>(x, Wh + 2*HID*HID, bv, Vp, smraw, m0, n0);
}

__global__ __launch_bounds__(256, 2)
void gemm_out(const __half* __restrict__ A, const __half* __restrict__ W,
              const float* __restrict__ bias, float* __restrict__ out)
{
    extern __shared__ char smraw[];
    gemm_core<0>(A, W, bias, out, smraw, blockIdx.x << 7, blockIdx.y << 7);
}

// ---------------------------------------------------------------------------
// Flash attention (R13 arithmetic), occupancy-optimized:
//   Q tile lives in SMEM (A-fragments via ldsm each k-step, not registers)
//   __launch_bounds__(256, 3) -> 84-reg cap -> 3 CTAs/SM -> 6 warps/SMSP.
// S = QK^T fp16; exp via ex2.approx.f16x2 (output = PV A-fragment);
// l via ones-vector mma.  8 warps x 16 query rows; 64-key tiles; 2-buffer.
// Smem: Q[0,18432) K0[18432) K1[27648) V0[36864) V1[46080); total 55296.
// ---------------------------------------------------------------------------
#define ASTR_B 144                 // 72 halves
#define ABUF_B (64*ASTR_B)         // 9216
#define QTILE_B (128*ASTR_B)       // 18432
#define KOFF QTILE_B               // 18432
#define VOFF2 (QTILE_B + 2*ABUF_B) // 36864
__global__ __launch_bounds__(256, 3)
void attn_mma10(const __half* __restrict__ Q, const __half* __restrict__ K,
                const __half* __restrict__ V, __half* __restrict__ ctx)
{
    extern __shared__ char smraw[];
    const uint32_t sb = smem_u32(smraw);
    const int tid = threadIdx.x;
    const int lane = tid & 31, warp = tid >> 5;
    const int g = lane >> 2, t4 = lane & 3;
    const int lm = lane >> 3, lr8 = lane & 7;
    const uint32_t laneA = ((uint32_t)((lm & 1)*8 + lr8))*ASTR_B + (uint32_t)(lm >> 1)*16;
    const uint32_t laneK = ((uint32_t)((lm >> 1)*8 + lr8))*ASTR_B + (uint32_t)(lm & 1)*16;
    const uint32_t laneV = ((uint32_t)((lm & 1)*8 + lr8))*ASTR_B + (uint32_t)(lm >> 1)*16;
    const int b = blockIdx.z, h = blockIdx.y;
    const int q0 = blockIdx.x << 7;

    const __half* Qg = Q + ((size_t)(b*HH + h) * SS + q0) * DD;
    const __half* Kg = K + (size_t)(b*HH + h) * SS * DD;
    const __half* Vg = V + (size_t)(b*HH + h) * SS * DD;

    // prologue: Q tile (128 rows) + K/V tile 0 (64 rows each) via cp.async
    {
        #pragma unroll
        for (int i = 0; i < 4; i++) {          // Q: 1024 chunks
            const int cc = tid + i*256;
            const int row = cc >> 3, col = cc & 7;
            cpasync16(sb + row*ASTR_B + col*16, Qg + (size_t)row*DD + col*8);
        }
        #pragma unroll
        for (int i = 0; i < 2; i++) {          // K0,V0: 512 chunks each
            const int cc = tid + i*256;
            const int row = cc >> 3, col = cc & 7;
            cpasync16(sb + KOFF + row*ASTR_B + col*16, Kg + (size_t)row*DD + col*8);
            cpasync16(sb + VOFF2 + row*ASTR_B + col*16, Vg + (size_t)row*DD + col*8);
        }
        CP_COMMIT();
        CP_WAIT0();
    }
    __syncthreads();

    const uint32_t qbase = sb + (uint32_t)(warp*16)*ASTR_B + laneA;

    float o[8][4];
    #pragma unroll
    for (int j = 0; j < 8; j++)
        #pragma unroll
        for (int k = 0; k < 4; k++) o[j][k] = 0.0f;
    float m0r = -1.0e30f, m1r = -1.0e30f, l0r = 0.0f, l1r = 0.0f;
    const uint32_t bones[2] = {0x3C003C00u, 0x3C003C00u};   // fp16 {1,1},{1,1}

    #pragma unroll 1
    for (int t = 0; t < SS/64; t++) {
        const int cur = t & 1;
        const uint32_t kbase = sb + KOFF + cur*ABUF_B + laneK;
        const uint32_t vbase = sb + VOFF2 + cur*ABUF_B + laneV;

        if (t < SS/64 - 1) {
            const uint32_t kd = sb + KOFF + (cur^1)*ABUF_B;
            const uint32_t vd = sb + VOFF2 + (cur^1)*ABUF_B;
            const __half* kn = Kg + (size_t)(t+1)*64*DD;
            const __half* vn = Vg + (size_t)(t+1)*64*DD;
            #pragma unroll
            for (int i = 0; i < 2; i++) {
                const int cc = tid + i*256;
                const int row = cc >> 3, col = cc & 7;
                cpasync16(kd + row*ASTR_B + col*16, kn + (size_t)row*DD + col*8);
                cpasync16(vd + row*ASTR_B + col*16, vn + (size_t)row*DD + col*8);
            }
            CP_COMMIT();
        }

        // S = Q K^T  (Q A-fragments via ldsm from smem each k-step)
        float sc[8][4];
        #pragma unroll
        for (int j = 0; j < 8; j++)
            #pragma unroll
            for (int k = 0; k < 4; k++) sc[j][k] = 0.0f;
        #pragma unroll
        for (int ks = 0; ks < 4; ks++) {
            uint32_t qa[4];
            ldsm4(qa, qbase + ks*32);
            #pragma unroll
            for (int p = 0; p < 4; p++) {
                uint32_t bf[4];
                ldsm4(bf, kbase + (uint32_t)(p*16)*ASTR_B + ks*32);
                mma16(sc[2*p],   qa, bf);
                mma16(sc[2*p+1], qa, bf+2);
            }
        }

        // online softmax (base-2): rows g and g+8
        float mx0 = -1.0e30f, mx1 = -1.0e30f;
        #pragma unroll
        for (int nt = 0; nt < 8; nt++) {
            mx0 = fmaxf(mx0, fmaxf(sc[nt][0], sc[nt][1]));
            mx1 = fmaxf(mx1, fmaxf(sc[nt][2], sc[nt][3]));
        }
        mx0 = fmaxf(mx0, __shfl_xor_sync(0xffffffffu, mx0, 1));
        mx0 = fmaxf(mx0, __shfl_xor_sync(0xffffffffu, mx0, 2));
        mx1 = fmaxf(mx1, __shfl_xor_sync(0xffffffffu, mx1, 1));
        mx1 = fmaxf(mx1, __shfl_xor_sync(0xffffffffu, mx1, 2));
        const float mn0 = fmaxf(m0r, mx0), mn1 = fmaxf(m1r, mx1);
        const float corr0 = ex2(m0r - mn0), corr1 = ex2(m1r - mn1);
        m0r = mn0; m1r = mn1;

        // P = 2^(S - m), packed fp16, via f16x2 MUFU (output = PV A-fragments)
        uint32_t af[4][4];
        #pragma unroll
        for (int j = 0; j < 4; j++) {
            af[j][0] = hex2(pkhf(sc[2*j][0]   - mn0, sc[2*j][1]   - mn0));
            af[j][1] = hex2(pkhf(sc[2*j][2]   - mn1, sc[2*j][3]   - mn1));
            af[j][2] = hex2(pkhf(sc[2*j+1][0] - mn0, sc[2*j+1][1] - mn0));
            af[j][3] = hex2(pkhf(sc[2*j+1][2] - mn1, sc[2*j+1][3] - mn1));
        }

        // l partial via ones-mma: lacc[0]/[2] = full 64-key row sums of fp16 P
        float lacc[4] = {0.0f, 0.0f, 0.0f, 0.0f};
        #pragma unroll
        for (int j = 0; j < 4; j++) mma16(lacc, af[j], bones);
        l0r = l0r * corr0 + lacc[0];
        l1r = l1r * corr1 + lacc[2];

        // rescale O
        #pragma unroll
        for (int nt = 0; nt < 8; nt++) {
            o[nt][0] *= corr0; o[nt][1] *= corr0;
            o[nt][2] *= corr1; o[nt][3] *= corr1;
        }

        // PV: O += P V
        #pragma unroll
        for (int j = 0; j < 4; j++) {
            #pragma unroll
            for (int p = 0; p < 4; p++) {
                uint32_t bf[4];
                ldsm4t(bf, vbase + (uint32_t)(j*16)*ASTR_B + p*32);
                mma16(o[2*p],   af[j], bf);
                mma16(o[2*p+1], af[j], bf+2);
            }
        }

        CP_WAIT0();
        __syncthreads();
    }

    // epilogue: l is the full row sum (ones-mma); normalize, write fp16 ctx
    const float inv0 = 1.0f / l0r, inv1 = 1.0f / l1r;
    const int row = q0 + warp*16 + g;
    #pragma unroll
    for (int nt = 0; nt < 8; nt++) {
        const int d = 8*nt + 2*t4;
        __half* p = ctx + ((size_t)b * SS + row) * HID + h*DD + d;
        *(uint32_t*)p = pkhf(o[nt][0]*inv0, o[nt][1]*inv0);
        *(uint32_t*)(p + 8*HID) = pkhf(o[nt][2]*inv1, o[nt][3]*inv1);
    }
}

// ---------------------------------------------------------------------------
extern "C" void kernel_launch(void* const* d_in, const int* in_sizes, int n_in,
                              void* d_out, int out_size)
{
    (void)in_sizes; (void)n_in; (void)out_size;
    const float* x  = (const float*)d_in[0];
    const float* Wq = (const float*)d_in[1];
    const float* bq = (const float*)d_in[2];
    const float* Wk = (const float*)d_in[3];
    const float* bk = (const float*)d_in[4];
    const float* Wv = (const float*)d_in[5];
    const float* bv = (const float*)d_in[6];
    const float* Wo = (const float*)d_in[7];
    const float* bo = (const float*)d_in[8];
    float* out = (float*)d_out;

    __half *Xp, *Wp, *Qp, *Kp, *Vp, *Cp;
    cudaGetSymbolAddress((void**)&Xp, g_X);
    cudaGetSymbolAddress((void**)&Wp, g_Wh);
    cudaGetSymbolAddress((void**)&Qp, g_Q);
    cudaGetSymbolAddress((void**)&Kp, g_K);
    cudaGetSymbolAddress((void**)&Vp, g_V);
    cudaGetSymbolAddress((void**)&Cp, g_C);

    const int gemm_smem = 2*GSTAGE_B + 512;        // 74240
    const int attn_smem = QTILE_B + 4*ABUF_B;      // 55296
    cudaFuncSetAttribute(gemm_qkv, cudaFuncAttributeMaxDynamicSharedMemorySize, gemm_smem);
    cudaFuncSetAttribute(gemm_out, cudaFuncAttributeMaxDynamicSharedMemorySize, gemm_smem);
    cudaFuncSetAttribute(attn_mma10, cudaFuncAttributeMaxDynamicSharedMemorySize, attn_smem);

    cvt_inputs<<<5120, 256>>>(x, Wq, Wk, Wv, Wo, Xp, Wp);

    gemm_qkv<<<dim3(MT/128, HID/128, 3), 256, gemm_smem>>>(
        Xp, Wp, bq, bk, bv, Qp, Kp, Vp);

    attn_mma10<<<dim3(SS/128, HH, BB), 256, attn_smem>>>(Qp, Kp, Vp, Cp);

    gemm_out<<<dim3(MT/128, HID/128), 256, gemm_smem>>>(Cp, Wp + 3*HID*HID, bo, out);
}

// round 17
// speedup vs baseline: 1.0885x; 1.0885x over previous
#include <cuda_runtime.h>
#include <cuda_fp16.h>
#include <cstdint>

// ---------------- problem constants ----------------
#define BB 4
#define SS 2048
#define HH 8
#define DD 64
#define HID 512
#define MT (BB*SS)   // 8192

// scratch (all fp16 intermediates)
__device__ __half g_X[MT*HID];        // x fp16
__device__ __half g_Wh[4*HID*HID];    // Wq,Wk,Wv,Wo fp16
__device__ __half g_Q[MT*HID];        // [b,h,s,d] pre-scaled by 0.125*log2e
__device__ __half g_K[MT*HID];        // [b,h,s,d]
__device__ __half g_V[MT*HID];        // [b,h,s,d]
__device__ __half g_C[MT*HID];        // ctx [b,s,hid] fp16

#define QSCALE 0.18033688011112042f   // 0.125 * log2(e)

__device__ __forceinline__ float ex2(float x){
    float r; asm("ex2.approx.ftz.f32 %0, %1;" : "=f"(r) : "f"(x)); return r;
}
// packed fp16 ex2: two exponentials in ONE MUFU op
__device__ __forceinline__ uint32_t hex2(uint32_t x){
    uint32_t r; asm("ex2.approx.f16x2 %0, %1;" : "=r"(r) : "r"(x)); return r;
}
__device__ __forceinline__ uint32_t pkhf(float lo, float hi){
    uint32_t d; asm("cvt.rn.f16x2.f32 %0, %1, %2;" : "=r"(d) : "f"(hi), "f"(lo)); return d;
}
__device__ __forceinline__ uint32_t smem_u32(const void* p){
    uint32_t a;
    asm("{ .reg .u64 t; cvta.to.shared.u64 t, %1; cvt.u32.u64 %0, t; }" : "=r"(a) : "l"(p));
    return a;
}
__device__ __forceinline__ void cpasync16(uint32_t dst, const void* src){
    asm volatile("cp.async.cg.shared.global [%0], [%1], 16;" :: "r"(dst), "l"(src) : "memory");
}
#define CP_COMMIT() asm volatile("cp.async.commit_group;" ::: "memory")
#define CP_WAIT0()  asm volatile("cp.async.wait_group 0;" ::: "memory")

// mma.sync m16n8k16 f16 (fp32 accumulate)
__device__ __forceinline__ void mma16(float* c, const uint32_t* a, const uint32_t* b){
    asm volatile("mma.sync.aligned.m16n8k16.row.col.f32.f16.f16.f32 "
        "{%0,%1,%2,%3}, {%4,%5,%6,%7}, {%8,%9}, {%0,%1,%2,%3};"
        : "+f"(c[0]), "+f"(c[1]), "+f"(c[2]), "+f"(c[3])
        : "r"(a[0]), "r"(a[1]), "r"(a[2]), "r"(a[3]), "r"(b[0]), "r"(b[1]));
}
__device__ __forceinline__ void ldsm4(uint32_t* r, uint32_t addr){
    asm volatile("ldmatrix.sync.aligned.m8n8.x4.shared.b16 {%0,%1,%2,%3}, [%4];"
        : "=r"(r[0]), "=r"(r[1]), "=r"(r[2]), "=r"(r[3]) : "r"(addr));
}
__device__ __forceinline__ void ldsm4t(uint32_t* r, uint32_t addr){
    asm volatile("ldmatrix.sync.aligned.m8n8.x4.trans.shared.b16 {%0,%1,%2,%3}, [%4];"
        : "=r"(r[0]), "=r"(r[1]), "=r"(r[2]), "=r"(r[3]) : "r"(addr));
}

// ---------------------------------------------------------------------------
// fp32 -> fp16 pre-conversion.  4 independent float4s per thread (MLP=4).
// Rounding points identical to the in-GEMM cvt of earlier rounds.
// Total float4s = 1048576 (x) + 262144 (4 weights) = 1310720 = 1280*256*4.
// ---------------------------------------------------------------------------
__global__ __launch_bounds__(256)
void cvt_inputs(const float* __restrict__ x,
                const float* __restrict__ Wq, const float* __restrict__ Wk,
                const float* __restrict__ Wv, const float* __restrict__ Wo,
                __half* __restrict__ Xh, __half* __restrict__ Wh)
{
    const int base = blockIdx.x * 256 + threadIdx.x;
    #pragma unroll
    for (int k = 0; k < 4; k++) {
        const int flat = base + k * 327680;
        const float* src; uint2* dst; int off;
        if (flat < 1048576) { src = x; dst = (uint2*)Xh; off = flat; }
        else {
            const int w = (flat - 1048576) >> 16;
            off = (flat - 1048576) & 65535;
            src = (w == 0) ? Wq : (w == 1) ? Wk : (w == 2) ? Wv : Wo;
            dst = (uint2*)(Wh + (size_t)w * HID * HID);
        }
        float4 v = ((const float4*)src)[off];
        dst[off] = make_uint2(pkhf(v.x, v.y), pkhf(v.z, v.w));
    }
}

// ---------------------------------------------------------------------------
// GEMM core (fp16 in gmem): out = A[M,512] @ W[Nblk,512]^T + bias.
// CTA 128x128, BK=64, 8 warps = 4(M) x 2(N).  2-stage cp.async pipeline with
// ONE __syncthreads per chunk.
// Tile stride 72 halves = 144 B (LDSM conflict-free).
// MODE 0: fp32 [m][512]   MODE 1: K fp16 [b,h,s,d]   MODE 2: Q scaled fp16
// MODE 3: V fp16 [b,h,s,d]
// ---------------------------------------------------------------------------
#define BK 64
#define GSTR_B 144
#define GAB_B (128*GSTR_B)       // per-matrix stage bytes = 18432
#define GSTAGE_B (2*GAB_B)       // 36864
#define NCH (HID/BK)             // 8

template<int MODE>
__device__ __forceinline__ void gemm_core(
    const __half* __restrict__ A, const __half* __restrict__ W,
    const float* __restrict__ bias, void* __restrict__ outv,
    char* smraw, int m0, int n0)
{
    float* bs = (float*)(smraw + 2*GSTAGE_B);
    const uint32_t sb = smem_u32(smraw);

    const int tid = threadIdx.x;
    const int lane = tid & 31, warp = tid >> 5;
    const int g = lane >> 2, t4 = lane & 3;
    const int warpM = warp >> 1, warpN = warp & 1;
    const int lm = lane >> 3, lr8 = lane & 7;
    const uint32_t laneA = ((uint32_t)((lm & 1)*8 + lr8))*GSTR_B + (uint32_t)(lm >> 1)*16;
    const uint32_t laneB = ((uint32_t)((lm >> 1)*8 + lr8))*GSTR_B + (uint32_t)(lm & 1)*16;

    if (tid < 128) bs[tid] = bias[n0 + tid];

    float c[2][8][4];
    #pragma unroll
    for (int i = 0; i < 2; i++)
        #pragma unroll
        for (int j = 0; j < 8; j++)
            #pragma unroll
            for (int k = 0; k < 4; k++) c[i][j][k] = 0.0f;

    const __half* Abase = A + (size_t)m0 * HID;
    const __half* Wbase = W + (size_t)n0 * HID;

    // prologue: chunk 0 -> stage 0
    #pragma unroll
    for (int i = 0; i < 4; i++) {
        const int cc = tid + i*256;
        const int row = cc >> 3, col = cc & 7;
        cpasync16(sb + row*GSTR_B + col*16, Abase + (size_t)row*HID + col*8);
        cpasync16(sb + GAB_B + row*GSTR_B + col*16, Wbase + (size_t)row*HID + col*8);
    }
    CP_COMMIT();

    #pragma unroll 1
    for (int ch = 0; ch < NCH; ch++) {
        const int cur = ch & 1;
        CP_WAIT0();
        __syncthreads();

        if (ch < NCH-1) {
            const uint32_t st = sb + (cur^1)*GSTAGE_B;
            const int koff = (ch+1)*BK;
            #pragma unroll
            for (int i = 0; i < 4; i++) {
                const int cc = tid + i*256;
                const int row = cc >> 3, col = cc & 7;
                cpasync16(st + row*GSTR_B + col*16, Abase + (size_t)row*HID + koff + col*8);
                cpasync16(st + GAB_B + row*GSTR_B + col*16, Wbase + (size_t)row*HID + koff + col*8);
            }
            CP_COMMIT();
        }

        const uint32_t abase = sb + cur*GSTAGE_B + (uint32_t)(warpM*32)*GSTR_B + laneA;
        const uint32_t bbase = sb + cur*GSTAGE_B + GAB_B + (uint32_t)(warpN*64)*GSTR_B + laneB;
        #pragma unroll
        for (int ks = 0; ks < 4; ks++) {      // 4 k-steps of 16
            uint32_t af[2][4];
            ldsm4(af[0], abase + ks*32);
            ldsm4(af[1], abase + 16*GSTR_B + ks*32);
            #pragma unroll
            for (int p = 0; p < 4; p++) {     // 16-n blocks
                uint32_t bf[4];
                ldsm4(bf, bbase + (uint32_t)(p*16)*GSTR_B + ks*32);
                mma16(c[0][2*p],   af[0], bf);
                mma16(c[0][2*p+1], af[0], bf+2);
                mma16(c[1][2*p],   af[1], bf);
                mma16(c[1][2*p+1], af[1], bf+2);
            }
        }
    }

    // epilogue
    #pragma unroll
    for (int mt = 0; mt < 2; mt++) {
        const int row = m0 + warpM*32 + mt*16 + g;
        #pragma unroll
        for (int nt = 0; nt < 8; nt++) {
            const int lc2 = warpN*64 + nt*8 + 2*t4;
            const float b0 = bs[lc2], b1 = bs[lc2+1];
            float2 v0 = make_float2(c[mt][nt][0] + b0, c[mt][nt][1] + b1);
            float2 v1 = make_float2(c[mt][nt][2] + b0, c[mt][nt][3] + b1);
            if (MODE == 2) { v0.x *= QSCALE; v0.y *= QSCALE; v1.x *= QSCALE; v1.y *= QSCALE; }
            if (MODE == 0) {
                float* out = (float*)outv;
                *(float2*)&out[(size_t)row * HID + n0 + lc2] = v0;
                *(float2*)&out[(size_t)(row+8) * HID + n0 + lc2] = v1;
            } else {
                __half* out = (__half*)outv;
                const int bi = row >> 11, s = row & 2047;
                const int cg = n0 + lc2;
                const int h = cg >> 6, d = cg & 63;
                __half* p = out + (((size_t)(bi*HH + h) * SS) + s) * DD + d;
                *(uint32_t*)p = pkhf(v0.x, v0.y);
                *(uint32_t*)(p + 8*DD) = pkhf(v1.x, v1.y);
            }
        }
    }
}

// fused QKV projection
__global__ __launch_bounds__(256, 2)
void gemm_qkv(const __half* __restrict__ x, const __half* __restrict__ Wh,
              const float* __restrict__ bq, const float* __restrict__ bk,
              const float* __restrict__ bv,
              __half* __restrict__ Qp, __half* __restrict__ Kp, __half* __restrict__ Vp)
{
    extern __shared__ char smraw[];
    const int m0 = blockIdx.x << 7, n0 = blockIdx.y << 7;
    if (blockIdx.z == 0)      gemm_core<2>(x, Wh,             bq, Qp, smraw, m0, n0);
    else if (blockIdx.z == 1) gemm_core<1>(x, Wh +   HID*HID, bk, Kp, smraw, m0, n0);
    else                      gemm_core<3>(x, Wh + 2*HID*HID, bv, Vp, smraw, m0, n0);
}

__global__ __launch_bounds__(256, 2)
void gemm_out(const __half* __restrict__ A, const __half* __restrict__ W,
              const float* __restrict__ bias, float* __restrict__ out)
{
    extern __shared__ char smraw[];
    gemm_core<0>(A, W, bias, out, smraw, blockIdx.x << 7, blockIdx.y << 7);
}

// ---------------------------------------------------------------------------
// Flash attention, all-fp16 operands (fp32 accum/softmax stats).
// S = QK^T fp16 m16n8k16; softmax exp via ex2.approx.f16x2 (2 exps / MUFU op),
// whose output IS the PV A-fragment; row-sum l computed by a ones-vector mma
// (exact consistency with the fp16 P used in PV; no quad reduction needed).
// 8 warps x 16 query rows; 64-key tiles, cp.async double buffer.
// ---------------------------------------------------------------------------
#define ASTR_B 144                 // 72 halves
#define ABUF_B (64*ASTR_B)         // 9216
// bytes: K0=0, K1=9216, V0=18432, V1=27648; total 36864
__global__ __launch_bounds__(256, 2)
void attn_mma7(const __half* __restrict__ Q, const __half* __restrict__ K,
               const __half* __restrict__ V, __half* __restrict__ ctx)
{
    extern __shared__ char smraw[];
    const uint32_t sb = smem_u32(smraw);
    const int tid = threadIdx.x;
    const int lane = tid & 31, warp = tid >> 5;
    const int g = lane >> 2, t4 = lane & 3;
    const int lm = lane >> 3, lr8 = lane & 7;
    const uint32_t laneK = ((uint32_t)((lm >> 1)*8 + lr8))*ASTR_B + (uint32_t)(lm & 1)*16;
    const uint32_t laneV = ((uint32_t)((lm & 1)*8 + lr8))*ASTR_B + (uint32_t)(lm >> 1)*16;
    const int b = blockIdx.z, h = blockIdx.y;
    const int q0 = blockIdx.x << 7;

    const __half* Qg = Q + ((size_t)(b*HH + h) * SS + q0) * DD;
    const __half* Kg = K + (size_t)(b*HH + h) * SS * DD;
    const __half* Vg = V + (size_t)(b*HH + h) * SS * DD;

    // Q fragments (rows 16*warp+g, +8): 4 k-steps of 16
    uint32_t qf[4][4];
    {
        const uint32_t* q0p = (const uint32_t*)(Qg + (size_t)(warp*16 + g) * DD);
        const uint32_t* q1p = q0p + 256;   // +8 rows * 64 halves = 256 u32
        #pragma unroll
        for (int ks = 0; ks < 4; ks++) {
            qf[ks][0] = q0p[8*ks + t4];
            qf[ks][1] = q1p[8*ks + t4];
            qf[ks][2] = q0p[8*ks + 4 + t4];
            qf[ks][3] = q1p[8*ks + 4 + t4];
        }
    }

    // prologue
    {
        #pragma unroll
        for (int i = 0; i < 2; i++) {
            const int cc = tid + i*256;
            const int row = cc >> 3, col = cc & 7;
            cpasync16(sb + row*ASTR_B + col*16, Kg + (size_t)row*DD + col*8);
            cpasync16(sb + 18432 + row*ASTR_B + col*16, Vg + (size_t)row*DD + col*8);
        }
        CP_COMMIT();
        CP_WAIT0();
    }
    __syncthreads();

    float o[8][4];
    #pragma unroll
    for (int j = 0; j < 8; j++)
        #pragma unroll
        for (int k = 0; k < 4; k++) o[j][k] = 0.0f;
    float m0r = -1.0e30f, m1r = -1.0e30f, l0r = 0.0f, l1r = 0.0f;
    const uint32_t bones[2] = {0x3C003C00u, 0x3C003C00u};   // fp16 {1,1},{1,1}

    #pragma unroll 1
    for (int t = 0; t < SS/64; t++) {
        const int cur = t & 1;
        const uint32_t kbase = sb + cur*ABUF_B + laneK;
        const uint32_t vbase = sb + 18432 + cur*ABUF_B + laneV;

        if (t < SS/64 - 1) {
            const uint32_t kd = sb + (cur^1)*ABUF_B;
            const uint32_t vd = sb + 18432 + (cur^1)*ABUF_B;
            const __half* kn = Kg + (size_t)(t+1)*64*DD;
            const __half* vn = Vg + (size_t)(t+1)*64*DD;
            #pragma unroll
            for (int i = 0; i < 2; i++) {
                const int cc = tid + i*256;
                const int row = cc >> 3, col = cc & 7;
                cpasync16(kd + row*ASTR_B + col*16, kn + (size_t)row*DD + col*8);
                cpasync16(vd + row*ASTR_B + col*16, vn + (size_t)row*DD + col*8);
            }
            CP_COMMIT();
        }

        // S = Q K^T
        float sc[8][4];
        #pragma unroll
        for (int j = 0; j < 8; j++)
            #pragma unroll
            for (int k = 0; k < 4; k++) sc[j][k] = 0.0f;
        #pragma unroll
        for (int ks = 0; ks < 4; ks++) {
            #pragma unroll
            for (int p = 0; p < 4; p++) {
                uint32_t bf[4];
                ldsm4(bf, kbase + (uint32_t)(p*16)*ASTR_B + ks*32);
                mma16(sc[2*p],   qf[ks], bf);
                mma16(sc[2*p+1], qf[ks], bf+2);
            }
        }

        // online softmax (base-2): rows g and g+8
        float mx0 = -1.0e30f, mx1 = -1.0e30f;
        #pragma unroll
        for (int nt = 0; nt < 8; nt++) {
            mx0 = fmaxf(mx0, fmaxf(sc[nt][0], sc[nt][1]));
            mx1 = fmaxf(mx1, fmaxf(sc[nt][2], sc[nt][3]));
        }
        mx0 = fmaxf(mx0, __shfl_xor_sync(0xffffffffu, mx0, 1));
        mx0 = fmaxf(mx0, __shfl_xor_sync(0xffffffffu, mx0, 2));
        mx1 = fmaxf(mx1, __shfl_xor_sync(0xffffffffu, mx1, 1));
        mx1 = fmaxf(mx1, __shfl_xor_sync(0xffffffffu, mx1, 2));
        const float mn0 = fmaxf(m0r, mx0), mn1 = fmaxf(m1r, mx1);
        const float corr0 = ex2(m0r - mn0), corr1 = ex2(m1r - mn1);
        m0r = mn0; m1r = mn1;

        // P = 2^(S - m), packed fp16, via f16x2 MUFU (output = PV A-fragments)
        uint32_t af[4][4];
        #pragma unroll
        for (int j = 0; j < 4; j++) {
            af[j][0] = hex2(pkhf(sc[2*j][0]   - mn0, sc[2*j][1]   - mn0));
            af[j][1] = hex2(pkhf(sc[2*j][2]   - mn1, sc[2*j][3]   - mn1));
            af[j][2] = hex2(pkhf(sc[2*j+1][0] - mn0, sc[2*j+1][1] - mn0));
            af[j][3] = hex2(pkhf(sc[2*j+1][2] - mn1, sc[2*j+1][3] - mn1));
        }

        // l partial via ones-mma: lacc[0]/[2] = full 64-key row sums of fp16 P
        float lacc[4] = {0.0f, 0.0f, 0.0f, 0.0f};
        #pragma unroll
        for (int j = 0; j < 4; j++) mma16(lacc, af[j], bones);
        l0r = l0r * corr0 + lacc[0];
        l1r = l1r * corr1 + lacc[2];

        // rescale O
        #pragma unroll
        for (int nt = 0; nt < 8; nt++) {
            o[nt][0] *= corr0; o[nt][1] *= corr0;
            o[nt][2] *= corr1; o[nt][3] *= corr1;
        }

        // PV: O += P V
        #pragma unroll
        for (int j = 0; j < 4; j++) {
            #pragma unroll
            for (int p = 0; p < 4; p++) {
                uint32_t bf[4];
                ldsm4t(bf, vbase + (uint32_t)(j*16)*ASTR_B + p*32);
                mma16(o[2*p],   af[j], bf);
                mma16(o[2*p+1], af[j], bf+2);
            }
        }

        CP_WAIT0();
        __syncthreads();
    }

    // epilogue: l is already the full row sum (ones-mma); normalize, write fp16
    const float inv0 = 1.0f / l0r, inv1 = 1.0f / l1r;
    const int row = q0 + warp*16 + g;
    #pragma unroll
    for (int nt = 0; nt < 8; nt++) {
        const int d = 8*nt + 2*t4;
        __half* p = ctx + ((size_t)b * SS + row) * HID + h*DD + d;
        *(uint32_t*)p = pkhf(o[nt][0]*inv0, o[nt][1]*inv0);
        *(uint32_t*)(p + 8*HID) = pkhf(o[nt][2]*inv1, o[nt][3]*inv1);
    }
}

// ---------------------------------------------------------------------------
extern "C" void kernel_launch(void* const* d_in, const int* in_sizes, int n_in,
                              void* d_out, int out_size)
{
    (void)in_sizes; (void)n_in; (void)out_size;
    const float* x  = (const float*)d_in[0];
    const float* Wq = (const float*)d_in[1];
    const float* bq = (const float*)d_in[2];
    const float* Wk = (const float*)d_in[3];
    const float* bk = (const float*)d_in[4];
    const float* Wv = (const float*)d_in[5];
    const float* bv = (const float*)d_in[6];
    const float* Wo = (const float*)d_in[7];
    const float* bo = (const float*)d_in[8];
    float* out = (float*)d_out;

    __half *Xp, *Wp, *Qp, *Kp, *Vp, *Cp;
    cudaGetSymbolAddress((void**)&Xp, g_X);
    cudaGetSymbolAddress((void**)&Wp, g_Wh);
    cudaGetSymbolAddress((void**)&Qp, g_Q);
    cudaGetSymbolAddress((void**)&Kp, g_K);
    cudaGetSymbolAddress((void**)&Vp, g_V);
    cudaGetSymbolAddress((void**)&Cp, g_C);

    const int gemm_smem = 2*GSTAGE_B + 512;   // 74240
    const int attn_smem = 36864;
    cudaFuncSetAttribute(gemm_qkv, cudaFuncAttributeMaxDynamicSharedMemorySize, gemm_smem);
    cudaFuncSetAttribute(gemm_out, cudaFuncAttributeMaxDynamicSharedMemorySize, gemm_smem);
    cudaFuncSetAttribute(attn_mma7, cudaFuncAttributeMaxDynamicSharedMemorySize, attn_smem);

    cvt_inputs<<<1280, 256>>>(x, Wq, Wk, Wv, Wo, Xp, Wp);

    gemm_qkv<<<dim3(MT/128, HID/128, 3), 256, gemm_smem>>>(
        Xp, Wp, bq, bk, bv, Qp, Kp, Vp);

    attn_mma7<<<dim3(SS/128, HH, BB), 256, attn_smem>>>(Qp, Kp, Vp, Cp);

    gemm_out<<<dim3(MT/128, HID/128), 256, gemm_smem>>>(Cp, Wp + 3*HID*HID, bo, out);
}